// round 4
// baseline (speedup 1.0000x reference)
#include <cuda_runtime.h>
#include <cstdint>

// SAG_4861902979729: X_out[i] = sum_{e in [rp[i], rp[i+1])} X[ci[e]]
// X [N=100000, D=100] f32. rp [N+1], ci [E] — dtype int32 OR int64 (JAX
// jax_enable_x64 ambiguity; R1's IMA is consistent with int32 data read as
// int64). Index width detected at runtime from rp's raw 32-bit words:
//   int32 data: words = [0, 32, 64, ...]   -> word[1] != 0
//   int64 data: words = [0, 0, 32, 0, ...] -> word[1] == 0 && word[2] != 0
// R3 bug fixed here: the probe is now two ALIGNED scalar int loads (the int2
// probe at byte offset 4 was a misaligned 8-byte load -> trap).
//
// Strategy: warp per row. Row = 100 f32 = 25 float4; lanes 0..24 each own one
// float4 accumulator (one LDG.E.128 per neighbor per lane). Neighbor indices
// loaded coalesced (one per lane) and broadcast via shfl. Unroll-by-4 over
// neighbors for MLP~4 to hide L2 latency (~234 cyc). Index stream uses __ldcs
// and output __stcs (evict-first) so the 40 MB X stays L2-resident.

#define D_DIM 100
#define VEC_PER_ROW 25   // 100 floats / 4 per float4

template <typename IT>
__device__ __forceinline__
void sag_row(const float* __restrict__ X,
             const IT* __restrict__ rp,
             const IT* __restrict__ ci,
             float* __restrict__ out,
             int row, int lane)
{
    const long long start = (long long)rp[row];
    const int deg = (int)((long long)rp[row + 1] - start);

    float4 acc = make_float4(0.f, 0.f, 0.f, 0.f);
    const bool active = (lane < VEC_PER_ROW);
    const size_t lane_off = (size_t)lane * 4;

    for (int k0 = 0; k0 < deg; k0 += 32) {
        const int cnt = min(32, deg - k0);
        // Coalesced streaming index load: one element per lane.
        int my_idx = 0;
        if (lane < cnt) my_idx = (int)__ldcs(ci + start + k0 + lane);

        int k = 0;
        for (; k + 4 <= cnt; k += 4) {
            const int j0 = __shfl_sync(0xffffffffu, my_idx, k + 0);
            const int j1 = __shfl_sync(0xffffffffu, my_idx, k + 1);
            const int j2 = __shfl_sync(0xffffffffu, my_idx, k + 2);
            const int j3 = __shfl_sync(0xffffffffu, my_idx, k + 3);
            if (active) {
                const float4 v0 = *(const float4*)(X + (size_t)j0 * D_DIM + lane_off);
                const float4 v1 = *(const float4*)(X + (size_t)j1 * D_DIM + lane_off);
                const float4 v2 = *(const float4*)(X + (size_t)j2 * D_DIM + lane_off);
                const float4 v3 = *(const float4*)(X + (size_t)j3 * D_DIM + lane_off);
                acc.x += v0.x + v1.x + v2.x + v3.x;
                acc.y += v0.y + v1.y + v2.y + v3.y;
                acc.z += v0.z + v1.z + v2.z + v3.z;
                acc.w += v0.w + v1.w + v2.w + v3.w;
            }
        }
        for (; k < cnt; k++) {
            const int j = __shfl_sync(0xffffffffu, my_idx, k);
            if (active) {
                const float4 v = *(const float4*)(X + (size_t)j * D_DIM + lane_off);
                acc.x += v.x; acc.y += v.y; acc.z += v.z; acc.w += v.w;
            }
        }
    }

    if (active) {
        __stcs((float4*)(out + (size_t)row * D_DIM + lane_off), acc);
    }
}

__global__ __launch_bounds__(256, 8)
void sag_warp_row_kernel(const float* __restrict__ X,
                         const void* __restrict__ rp_raw,
                         const void* __restrict__ ci_raw,
                         float* __restrict__ out,
                         int n)
{
    const int lane = threadIdx.x & 31;
    const int warp0 = (blockIdx.x * blockDim.x + threadIdx.x) >> 5;
    const int nwarps = (gridDim.x * blockDim.x) >> 5;

    // Runtime index-width probe: two ALIGNED scalar 4B loads (uniform result).
    const int* rp_words = (const int*)rp_raw;
    const int w1 = __ldg(rp_words + 1);
    const int w2 = __ldg(rp_words + 2);
    const bool is64 = (w1 == 0) && (w2 != 0);

    if (is64) {
        const long long* rp = (const long long*)rp_raw;
        const long long* ci = (const long long*)ci_raw;
        for (int row = warp0; row < n; row += nwarps)
            sag_row<long long>(X, rp, ci, out, row, lane);
    } else {
        const int* rp = (const int*)rp_raw;
        const int* ci = (const int*)ci_raw;
        for (int row = warp0; row < n; row += nwarps)
            sag_row<int>(X, rp, ci, out, row, lane);
    }
}

extern "C" void kernel_launch(void* const* d_in, const int* in_sizes, int n_in,
                              void* d_out, int out_size)
{
    const float* X   = (const float*)d_in[0];
    const void*  rp  = d_in[1];
    const void*  ci  = d_in[2];
    float*       out = (float*)d_out;

    const int n = in_sizes[1] - 1;           // row_pointers has N+1 entries

    const int threads = 256;                  // 8 warps/block
    const int warps_per_block = threads / 32;
    const int blocks = (n + warps_per_block - 1) / warps_per_block;

    sag_warp_row_kernel<<<blocks, threads>>>(X, rp, ci, out, n);
}

// round 5
// speedup vs baseline: 1.0259x; 1.0259x over previous
#include <cuda_runtime.h>
#include <cstdint>

// SAG_4861902979729: X_out[i] = sum_{e in [rp[i], rp[i+1])} X[ci[e]]
// X [N=100000, D=100] f32. rp [N+1], ci [E] int32 or int64 (runtime-detected
// from rp words; probe uses two ALIGNED scalar loads).
//
// R5: kernel is L1tex-bound (R4 ncu: L1=86.6%, L2=69%, DRAM=10.2%).
// Keep warp-per-row 25-lane float4 gather (wavefront-optimal for 400B rows),
// add a deg==32 fast path: indices loaded once (1 per lane), 32-neighbor body
// fully unrolled in 4 groups of 8 outstanding LDG.E.128 per lane -> MLP=8 to
// close the L1 stall slack. Streaming policy (__ldcs idx, __stcs out) keeps
// the 40 MB X L2-resident.

#define D_DIM 100
#define VEC_PER_ROW 25   // 100 floats / 4 per float4

__device__ __forceinline__ void acc_add(float4& a, const float4& v) {
    a.x += v.x; a.y += v.y; a.z += v.z; a.w += v.w;
}

template <typename IT>
__device__ __forceinline__
void sag_row_generic(const float* __restrict__ X,
                     const IT* __restrict__ ci,
                     long long start, int deg,
                     float4& acc, int lane, bool active, size_t lane_off)
{
    for (int k0 = 0; k0 < deg; k0 += 32) {
        const int cnt = min(32, deg - k0);
        int my_idx = 0;
        if (lane < cnt) my_idx = (int)__ldcs(ci + start + k0 + lane);
        for (int k = 0; k < cnt; k++) {
            const int j = __shfl_sync(0xffffffffu, my_idx, k);
            if (active) {
                const float4 v = *(const float4*)(X + (size_t)j * D_DIM + lane_off);
                acc_add(acc, v);
            }
        }
    }
}

template <typename IT>
__device__ __forceinline__
void sag_row(const float* __restrict__ X,
             const IT* __restrict__ rp,
             const IT* __restrict__ ci,
             float* __restrict__ out,
             int row, int lane)
{
    const long long start = (long long)rp[row];
    const int deg = (int)((long long)rp[row + 1] - start);

    float4 acc = make_float4(0.f, 0.f, 0.f, 0.f);
    const bool active = (lane < VEC_PER_ROW);
    const size_t lane_off = (size_t)lane * 4;

    if (deg == 32) {
        // Fast path: one coalesced index load, fully unrolled body.
        const int my_idx = (int)__ldcs(ci + start + lane);
        #pragma unroll
        for (int g = 0; g < 4; g++) {
            int j[8];
            #pragma unroll
            for (int u = 0; u < 8; u++)
                j[u] = __shfl_sync(0xffffffffu, my_idx, g * 8 + u);
            if (active) {
                float4 v[8];
                // 8 independent LDG.E.128 in flight per lane (MLP=8).
                #pragma unroll
                for (int u = 0; u < 8; u++)
                    v[u] = *(const float4*)(X + (size_t)j[u] * D_DIM + lane_off);
                // Pairwise tree sum, then into acc.
                #pragma unroll
                for (int u = 0; u < 4; u++) acc_add(v[u], v[u + 4]);
                acc_add(v[0], v[2]);
                acc_add(v[1], v[3]);
                acc_add(v[0], v[1]);
                acc_add(acc, v[0]);
            }
        }
    } else {
        sag_row_generic<IT>(X, ci, start, deg, acc, lane, active, lane_off);
    }

    if (active) {
        __stcs((float4*)(out + (size_t)row * D_DIM + lane_off), acc);
    }
}

__global__ __launch_bounds__(256)
void sag_warp_row_kernel(const float* __restrict__ X,
                         const void* __restrict__ rp_raw,
                         const void* __restrict__ ci_raw,
                         float* __restrict__ out,
                         int n)
{
    const int lane = threadIdx.x & 31;
    const int warp0 = (blockIdx.x * blockDim.x + threadIdx.x) >> 5;
    const int nwarps = (gridDim.x * blockDim.x) >> 5;

    // Runtime index-width probe: two ALIGNED scalar 4B loads (uniform result).
    // int32 rp: words [0,32,64,...] -> w1 != 0
    // int64 rp: words [0,0,32,0,..] -> w1 == 0 && w2 != 0
    const int* rp_words = (const int*)rp_raw;
    const int w1 = __ldg(rp_words + 1);
    const int w2 = __ldg(rp_words + 2);
    const bool is64 = (w1 == 0) && (w2 != 0);

    if (is64) {
        const long long* rp = (const long long*)rp_raw;
        const long long* ci = (const long long*)ci_raw;
        for (int row = warp0; row < n; row += nwarps)
            sag_row<long long>(X, rp, ci, out, row, lane);
    } else {
        const int* rp = (const int*)rp_raw;
        const int* ci = (const int*)ci_raw;
        for (int row = warp0; row < n; row += nwarps)
            sag_row<int>(X, rp, ci, out, row, lane);
    }
}

extern "C" void kernel_launch(void* const* d_in, const int* in_sizes, int n_in,
                              void* d_out, int out_size)
{
    const float* X   = (const float*)d_in[0];
    const void*  rp  = d_in[1];
    const void*  ci  = d_in[2];
    float*       out = (float*)d_out;

    const int n = in_sizes[1] - 1;           // row_pointers has N+1 entries

    const int threads = 256;                  // 8 warps/block
    const int warps_per_block = threads / 32;
    const int blocks = (n + warps_per_block - 1) / warps_per_block;

    sag_warp_row_kernel<<<blocks, threads>>>(X, rp, ci, out, n);
}